// round 1
// baseline (speedup 1.0000x reference)
#include <cuda_runtime.h>

// MultiHeadEMA as a chunked diagonal linear recurrence (no FFT).
// out[b,t,d] = sum_n c[d,n] * h[d,n,t] + omega[d]*x[b,t,d]
// h[t] = q*h[t-1] + x[t],  q = 1 - sigmoid(delta)*sigmoid(alpha),
// c = sigmoid(delta)*beta*gamma*sqrt(1/N)

#define cB 8
#define cL 4096
#define cD 1024
#define cN 16
#define cC 16            // chunks
#define cS (cL / cC)     // 256 steps per chunk
#define TD 128           // threads per block
#define cVEC 2           // channels per thread

typedef unsigned long long u64;

// scratch (static __device__ arrays: no allocations allowed)
__device__ float g_q[cD * cN];
__device__ float g_cc[cD * cN];
__device__ float g_qS[cD * cN];
__device__ float g_Le[(size_t)cB * cC * cD * cN];  // local chunk end states
__device__ float g_P[(size_t)cB * cC * cD * cN];   // prefix (init) states per chunk

__device__ __forceinline__ u64 pack2(float lo, float hi) {
    u64 r; asm("mov.b64 %0,{%1,%2};" : "=l"(r) : "f"(lo), "f"(hi)); return r;
}
__device__ __forceinline__ float2 unpack2(u64 v) {
    float2 f; asm("mov.b64 {%0,%1},%2;" : "=f"(f.x), "=f"(f.y) : "l"(v)); return f;
}
__device__ __forceinline__ u64 fma2(u64 a, u64 b, u64 c) {
    u64 d; asm("fma.rn.f32x2 %0,%1,%2,%3;" : "=l"(d) : "l"(a), "l"(b), "l"(c)); return d;
}
__device__ __forceinline__ u64 mul2(u64 a, u64 b) {
    u64 d; asm("mul.rn.f32x2 %0,%1,%2;" : "=l"(d) : "l"(a), "l"(b)); return d;
}

// ---------------------------------------------------------------------------
// Kernel 0: per-(d,n) coefficients
// ---------------------------------------------------------------------------
__global__ void coeff_kernel(const float* __restrict__ delta,
                             const float* __restrict__ alpha,
                             const float* __restrict__ beta,
                             const float* __restrict__ gamma) {
    int i = blockIdx.x * blockDim.x + threadIdx.x;
    if (i >= cD * cN) return;
    float p  = 1.f / (1.f + expf(-delta[i]));
    float a  = 1.f / (1.f + expf(-alpha[i]));
    float pa = p * a;
    g_q[i]  = 1.f - pa;
    g_cc[i] = p * beta[i] * gamma[i] * 0.25f;               // scale = sqrt(1/16)
    g_qS[i] = expf((float)cS * log1pf(-pa));                // q^S, accurate near q~1
}

// ---------------------------------------------------------------------------
// Kernel A: per-chunk local end states (zero initial state)
// ---------------------------------------------------------------------------
__device__ __forceinline__ void stepA(u64* h, const u64* q, float2 xv) {
    u64 a0 = pack2(xv.x, xv.x), a1 = pack2(xv.y, xv.y);
#pragma unroll
    for (int j = 0; j < 8; j++) h[j] = fma2(q[j], h[j], a0);
#pragma unroll
    for (int j = 0; j < 8; j++) h[8 + j] = fma2(q[8 + j], h[8 + j], a1);
}

__global__ void __launch_bounds__(TD) local_kernel(const float* __restrict__ x) {
    int d0 = (blockIdx.x * TD + threadIdx.x) * cVEC;
    int c = blockIdx.y, b = blockIdx.z;
    u64 q[16], h[16];
#pragma unroll
    for (int j = 0; j < 8; j++) {
        float2 v = *(const float2*)(g_q + d0 * cN + 2 * j);
        float2 w = *(const float2*)(g_q + (d0 + 1) * cN + 2 * j);
        q[j] = pack2(v.x, v.y);
        q[8 + j] = pack2(w.x, w.y);
        h[j] = 0ULL; h[8 + j] = 0ULL;
    }
    const float* xp = x + ((size_t)b * cL + (size_t)c * cS) * cD + d0;
#pragma unroll 1
    for (int t = 0; t < cS; t += 4) {
        float2 x0 = *(const float2*)(xp);
        float2 x1 = *(const float2*)(xp + cD);
        float2 x2 = *(const float2*)(xp + 2 * cD);
        float2 x3 = *(const float2*)(xp + 3 * cD);
        xp += 4 * cD;
        stepA(h, q, x0); stepA(h, q, x1); stepA(h, q, x2); stepA(h, q, x3);
    }
    size_t pb = ((size_t)(b * cC + c) * cD + d0) * cN;
#pragma unroll
    for (int j = 0; j < 8; j++) {
        *(float2*)(g_Le + pb + 2 * j)      = unpack2(h[j]);
        *(float2*)(g_Le + pb + cN + 2 * j) = unpack2(h[8 + j]);
    }
}

// ---------------------------------------------------------------------------
// Kernel B: scan across chunks: P[c] = E[c-1], E[c] = q^S * E[c-1] + Le[c]
// ---------------------------------------------------------------------------
__global__ void scan_kernel() {
    int i = blockIdx.x * blockDim.x + threadIdx.x;
    if (i >= cB * cD * cN) return;
    int dn = i % (cD * cN);
    int b  = i / (cD * cN);
    float qS = g_qS[dn];
    size_t base = (size_t)b * cC * cD * cN + dn;
    float h = 0.f;
#pragma unroll
    for (int c = 0; c < cC; c++) {
        g_P[base + (size_t)c * cD * cN] = h;
        h = fmaf(qS, h, g_Le[base + (size_t)c * cD * cN]);
    }
}

// ---------------------------------------------------------------------------
// Kernel C: full recurrence per chunk with correct initial state + residual
// ---------------------------------------------------------------------------
__device__ __forceinline__ float2 stepC(u64* h, const u64* q, const u64* cc, float2 xv) {
    u64 a0 = pack2(xv.x, xv.x), a1 = pack2(xv.y, xv.y);
#pragma unroll
    for (int j = 0; j < 8; j++) h[j] = fma2(q[j], h[j], a0);
#pragma unroll
    for (int j = 0; j < 8; j++) h[8 + j] = fma2(q[8 + j], h[8 + j], a1);
    u64 s0 = mul2(cc[0], h[0]);
    u64 s1 = mul2(cc[8], h[8]);
#pragma unroll
    for (int j = 1; j < 8; j++) {
        s0 = fma2(cc[j], h[j], s0);
        s1 = fma2(cc[8 + j], h[8 + j], s1);
    }
    float2 f0 = unpack2(s0), f1 = unpack2(s1);
    return make_float2(f0.x + f0.y, f1.x + f1.y);
}

__global__ void __launch_bounds__(TD) main_kernel(const float* __restrict__ x,
                                                  const float* __restrict__ omega,
                                                  float* __restrict__ out) {
    int d0 = (blockIdx.x * TD + threadIdx.x) * cVEC;
    int c = blockIdx.y, b = blockIdx.z;
    u64 q[16], cc[16], h[16];
    size_t pb = ((size_t)(b * cC + c) * cD + d0) * cN;
#pragma unroll
    for (int j = 0; j < 8; j++) {
        float2 v  = *(const float2*)(g_q + d0 * cN + 2 * j);
        float2 w  = *(const float2*)(g_q + (d0 + 1) * cN + 2 * j);
        float2 cv = *(const float2*)(g_cc + d0 * cN + 2 * j);
        float2 cw = *(const float2*)(g_cc + (d0 + 1) * cN + 2 * j);
        float2 hv = *(const float2*)(g_P + pb + 2 * j);
        float2 hw = *(const float2*)(g_P + pb + cN + 2 * j);
        q[j] = pack2(v.x, v.y);   q[8 + j] = pack2(w.x, w.y);
        cc[j] = pack2(cv.x, cv.y); cc[8 + j] = pack2(cw.x, cw.y);
        h[j] = pack2(hv.x, hv.y);  h[8 + j] = pack2(hw.x, hw.y);
    }
    float w0 = omega[d0], w1 = omega[d0 + 1];
    size_t off = ((size_t)b * cL + (size_t)c * cS) * cD + d0;
    const float* xp = x + off;
    float* op = out + off;
#pragma unroll 1
    for (int t = 0; t < cS; t += 4) {
        float2 x0 = *(const float2*)(xp);
        float2 x1 = *(const float2*)(xp + cD);
        float2 x2 = *(const float2*)(xp + 2 * cD);
        float2 x3 = *(const float2*)(xp + 3 * cD);
        xp += 4 * cD;
        float2 o;
        o = stepC(h, q, cc, x0);
        *(float2*)(op)          = make_float2(o.x + x0.x * w0, o.y + x0.y * w1);
        o = stepC(h, q, cc, x1);
        *(float2*)(op + cD)     = make_float2(o.x + x1.x * w0, o.y + x1.y * w1);
        o = stepC(h, q, cc, x2);
        *(float2*)(op + 2 * cD) = make_float2(o.x + x2.x * w0, o.y + x2.y * w1);
        o = stepC(h, q, cc, x3);
        *(float2*)(op + 3 * cD) = make_float2(o.x + x3.x * w0, o.y + x3.y * w1);
        op += 4 * cD;
    }
}

// ---------------------------------------------------------------------------
extern "C" void kernel_launch(void* const* d_in, const int* in_sizes, int n_in,
                              void* d_out, int out_size) {
    const float* x     = (const float*)d_in[0];
    const float* delta = (const float*)d_in[1];
    const float* alpha = (const float*)d_in[2];
    const float* beta  = (const float*)d_in[3];
    const float* gamma = (const float*)d_in[4];
    const float* omega = (const float*)d_in[5];
    float* out = (float*)d_out;

    coeff_kernel<<<(cD * cN + 255) / 256, 256>>>(delta, alpha, beta, gamma);
    dim3 grid(cD / (TD * cVEC), cC, cB);
    local_kernel<<<grid, TD>>>(x);
    scan_kernel<<<(cB * cD * cN + 255) / 256, 256>>>();
    main_kernel<<<grid, TD>>>(x, omega, out);
}

// round 2
// speedup vs baseline: 1.2202x; 1.2202x over previous
#include <cuda_runtime.h>

// MultiHeadEMA as a chunked diagonal linear recurrence (no FFT).
// out[b,t,d] = sum_n c[d,n] * h[d,n,t] + omega[d]*x[b,t,d]
// h[t] = q*h[t-1] + x[t],  q = 1 - sigmoid(delta)*sigmoid(alpha),
// c = sigmoid(delta)*beta*gamma*sqrt(1/N)
//
// R2: 1 channel/thread (occupancy 19.5% -> ~44%), software-pipelined x
// prefetch, dot product as 2 chains + add2.

#define cB 8
#define cL 4096
#define cD 1024
#define cN 16
#define cC 16            // chunks
#define cS (cL / cC)     // 256 steps per chunk
#define TD 128           // threads per block (1 channel per thread)

typedef unsigned long long u64;

// scratch (static __device__ arrays: no allocations allowed)
__device__ float g_q[cD * cN];
__device__ float g_cc[cD * cN];
__device__ float g_qS[cD * cN];
__device__ float g_Le[(size_t)cB * cC * cD * cN];  // local chunk end states
__device__ float g_P[(size_t)cB * cC * cD * cN];   // prefix (init) states per chunk

__device__ __forceinline__ u64 pack2(float lo, float hi) {
    u64 r; asm("mov.b64 %0,{%1,%2};" : "=l"(r) : "f"(lo), "f"(hi)); return r;
}
__device__ __forceinline__ float2 unpack2(u64 v) {
    float2 f; asm("mov.b64 {%0,%1},%2;" : "=f"(f.x), "=f"(f.y) : "l"(v)); return f;
}
__device__ __forceinline__ u64 fma2(u64 a, u64 b, u64 c) {
    u64 d; asm("fma.rn.f32x2 %0,%1,%2,%3;" : "=l"(d) : "l"(a), "l"(b), "l"(c)); return d;
}
__device__ __forceinline__ u64 mul2(u64 a, u64 b) {
    u64 d; asm("mul.rn.f32x2 %0,%1,%2;" : "=l"(d) : "l"(a), "l"(b)); return d;
}
__device__ __forceinline__ u64 add2(u64 a, u64 b) {
    u64 d; asm("add.rn.f32x2 %0,%1,%2;" : "=l"(d) : "l"(a), "l"(b)); return d;
}

// ---------------------------------------------------------------------------
// Kernel 0: per-(d,n) coefficients
// ---------------------------------------------------------------------------
__global__ void coeff_kernel(const float* __restrict__ delta,
                             const float* __restrict__ alpha,
                             const float* __restrict__ beta,
                             const float* __restrict__ gamma) {
    int i = blockIdx.x * blockDim.x + threadIdx.x;
    if (i >= cD * cN) return;
    float p  = 1.f / (1.f + expf(-delta[i]));
    float a  = 1.f / (1.f + expf(-alpha[i]));
    float pa = p * a;
    g_q[i]  = 1.f - pa;
    g_cc[i] = p * beta[i] * gamma[i] * 0.25f;               // scale = sqrt(1/16)
    g_qS[i] = expf((float)cS * log1pf(-pa));                // q^S, accurate near q~1
}

// ---------------------------------------------------------------------------
// Kernel A: per-chunk local end states (zero initial state)
// ---------------------------------------------------------------------------
__device__ __forceinline__ void stepA(u64* h, const u64* q, float xv) {
    u64 a = pack2(xv, xv);
#pragma unroll
    for (int j = 0; j < 8; j++) h[j] = fma2(q[j], h[j], a);
}

__global__ void __launch_bounds__(TD, 8) local_kernel(const float* __restrict__ x) {
    int d = blockIdx.x * TD + threadIdx.x;      // channel index
    int c = blockIdx.y, b = blockIdx.z;
    u64 q[8], h[8];
#pragma unroll
    for (int j = 0; j < 8; j++) {
        float2 v = *(const float2*)(g_q + d * cN + 2 * j);
        q[j] = pack2(v.x, v.y);
        h[j] = 0ULL;
    }
    const float* xp = x + ((size_t)b * cL + (size_t)c * cS) * cD + d;
    float x0 = xp[0], x1 = xp[cD], x2 = xp[2 * cD], x3 = xp[3 * cD];
    xp += 4 * cD;
#pragma unroll 1
    for (int t = 0; t < cS; t += 4) {
        float y0, y1, y2, y3;
        if (t + 4 < cS) {
            y0 = xp[0]; y1 = xp[cD]; y2 = xp[2 * cD]; y3 = xp[3 * cD];
            xp += 4 * cD;
        }
        stepA(h, q, x0); stepA(h, q, x1); stepA(h, q, x2); stepA(h, q, x3);
        x0 = y0; x1 = y1; x2 = y2; x3 = y3;
    }
    size_t pb = ((size_t)(b * cC + c) * cD + d) * cN;
#pragma unroll
    for (int j = 0; j < 8; j++)
        *(float2*)(g_Le + pb + 2 * j) = unpack2(h[j]);
}

// ---------------------------------------------------------------------------
// Kernel B: scan across chunks: P[c] = E[c-1], E[c] = q^S * E[c-1] + Le[c]
// ---------------------------------------------------------------------------
__global__ void scan_kernel() {
    int i = blockIdx.x * blockDim.x + threadIdx.x;
    if (i >= cB * cD * cN) return;
    int dn = i % (cD * cN);
    int b  = i / (cD * cN);
    float qS = g_qS[dn];
    size_t base = (size_t)b * cC * cD * cN + dn;
    float h = 0.f;
#pragma unroll
    for (int c = 0; c < cC; c++) {
        g_P[base + (size_t)c * cD * cN] = h;
        h = fmaf(qS, h, g_Le[base + (size_t)c * cD * cN]);
    }
}

// ---------------------------------------------------------------------------
// Kernel C: full recurrence per chunk with correct initial state + residual
// ---------------------------------------------------------------------------
__device__ __forceinline__ float stepC(u64* h, const u64* q, const u64* cc,
                                       float xv, float w) {
    u64 a = pack2(xv, xv);
#pragma unroll
    for (int j = 0; j < 8; j++) h[j] = fma2(q[j], h[j], a);
    u64 s0 = mul2(cc[0], h[0]);
    u64 s1 = mul2(cc[1], h[1]);
    s0 = fma2(cc[2], h[2], s0);  s1 = fma2(cc[3], h[3], s1);
    s0 = fma2(cc[4], h[4], s0);  s1 = fma2(cc[5], h[5], s1);
    s0 = fma2(cc[6], h[6], s0);  s1 = fma2(cc[7], h[7], s1);
    float2 f = unpack2(add2(s0, s1));
    return f.x + f.y + xv * w;
}

__global__ void __launch_bounds__(TD, 7) main_kernel(const float* __restrict__ x,
                                                     const float* __restrict__ omega,
                                                     float* __restrict__ out) {
    int d = blockIdx.x * TD + threadIdx.x;      // channel index
    int c = blockIdx.y, b = blockIdx.z;
    u64 q[8], cc[8], h[8];
    size_t pb = ((size_t)(b * cC + c) * cD + d) * cN;
#pragma unroll
    for (int j = 0; j < 8; j++) {
        float2 v  = *(const float2*)(g_q  + d * cN + 2 * j);
        float2 cv = *(const float2*)(g_cc + d * cN + 2 * j);
        float2 hv = *(const float2*)(g_P  + pb + 2 * j);
        q[j]  = pack2(v.x, v.y);
        cc[j] = pack2(cv.x, cv.y);
        h[j]  = pack2(hv.x, hv.y);
    }
    float w = omega[d];
    size_t off = ((size_t)b * cL + (size_t)c * cS) * cD + d;
    const float* xp = x + off;
    float* op = out + off;
    float x0 = xp[0], x1 = xp[cD], x2 = xp[2 * cD], x3 = xp[3 * cD];
    xp += 4 * cD;
#pragma unroll 1
    for (int t = 0; t < cS; t += 4) {
        float y0, y1, y2, y3;
        if (t + 4 < cS) {
            y0 = xp[0]; y1 = xp[cD]; y2 = xp[2 * cD]; y3 = xp[3 * cD];
            xp += 4 * cD;
        }
        op[0]      = stepC(h, q, cc, x0, w);
        op[cD]     = stepC(h, q, cc, x1, w);
        op[2 * cD] = stepC(h, q, cc, x2, w);
        op[3 * cD] = stepC(h, q, cc, x3, w);
        op += 4 * cD;
        x0 = y0; x1 = y1; x2 = y2; x3 = y3;
    }
}

// ---------------------------------------------------------------------------
extern "C" void kernel_launch(void* const* d_in, const int* in_sizes, int n_in,
                              void* d_out, int out_size) {
    const float* x     = (const float*)d_in[0];
    const float* delta = (const float*)d_in[1];
    const float* alpha = (const float*)d_in[2];
    const float* beta  = (const float*)d_in[3];
    const float* gamma = (const float*)d_in[4];
    const float* omega = (const float*)d_in[5];
    float* out = (float*)d_out;

    coeff_kernel<<<(cD * cN + 255) / 256, 256>>>(delta, alpha, beta, gamma);
    dim3 grid(cD / TD, cC, cB);                 // (8, 16, 8) = 1024 CTAs
    local_kernel<<<grid, TD>>>(x);
    scan_kernel<<<(cB * cD * cN + 255) / 256, 256>>>();
    main_kernel<<<grid, TD>>>(x, omega, out);
}